// round 14
// baseline (speedup 1.0000x reference)
#include <cuda_runtime.h>
#include <cuda_bf16.h>
#include <cuda_fp16.h>
#include <cstdint>

// Problem constants
#define NROW 16384
#define DIMK 128
#define NTILES 16384        // 128 x 128 tiles of 128x128
#define NCTA 296            // persistent CTAs, 2 per SM

// log2(e) * 5  (exp(x/T) = 2^(x*5*log2e), T = 0.2) — folded into v1 at prep.
#define K_EXP2 7.2134752044448170f

// Scratch (static device globals — no runtime allocation)
static __device__ __align__(16) __nv_bfloat16 g_v1[NROW * DIMK];  // pre-scaled by K_EXP2
static __device__ __align__(16) __nv_bfloat16 g_v2[NROW * DIMK];
static __device__ float g_rowsum[NROW];
static __device__ float g_diag_part[NROW / 4];

__device__ __forceinline__ uint32_t smem_u32(const void* p) {
    uint32_t a;
    asm("{ .reg .u64 t; cvta.to.shared.u64 t, %1; cvt.u32.u64 %0, t; }"
        : "=r"(a) : "l"(p));
    return a;
}

__device__ __forceinline__ void cp_async16(uint32_t smem_dst, const void* gsrc) {
    asm volatile("cp.async.cg.shared.global [%0], [%1], 16;"
                 :: "r"(smem_dst), "l"(gsrc) : "memory");
}

__device__ __forceinline__ void ldsm4(uint32_t* r, uint32_t addr) {
    asm volatile("ldmatrix.sync.aligned.m8n8.x4.shared.b16 {%0,%1,%2,%3}, [%4];"
                 : "=r"(r[0]), "=r"(r[1]), "=r"(r[2]), "=r"(r[3]) : "r"(addr));
}

__device__ __forceinline__ void mma16816(float* d, const uint32_t* a, const uint32_t* b) {
    asm volatile(
        "mma.sync.aligned.m16n8k16.row.col.f32.bf16.bf16.f32 "
        "{%0,%1,%2,%3}, {%4,%5,%6,%7}, {%8,%9}, {%0,%1,%2,%3};"
        : "+f"(d[0]), "+f"(d[1]), "+f"(d[2]), "+f"(d[3])
        : "r"(a[0]), "r"(a[1]), "r"(a[2]), "r"(a[3]), "r"(b[0]), "r"(b[1]));
}

__device__ __forceinline__ uint32_t cvt_f16x2(float lo, float hi) {
    uint32_t r;
    asm("cvt.rn.f16x2.f32 %0, %1, %2;" : "=r"(r) : "f"(hi), "f"(lo));
    return r;
}
__device__ __forceinline__ uint32_t ex2_f16x2(uint32_t x) {
    uint32_t r;
    asm("ex2.approx.f16x2 %0, %1;" : "=r"(r) : "r"(x));
    return r;
}

// ---------------------------------------------------------------------------
// Kernel 1: normalize rows (fp32), emit bf16 copies (v1 pre-scaled by K_EXP2),
// per-block diag partials (fp32-exact), zero g_rowsum, zero out[0].
// One warp per row; 4 warps per block.
// ---------------------------------------------------------------------------
__global__ void __launch_bounds__(128) cl_prep(const float* __restrict__ emb,
                                               float* __restrict__ out) {
    __shared__ float sh_diag[4];
    int wid = threadIdx.x >> 5, lane = threadIdx.x & 31;
    int row = blockIdx.x * 4 + wid;

    const float4* r0 = (const float4*)(emb) + (size_t)row * (DIMK / 4) + lane;
    const float4* r1 = (const float4*)(emb + (size_t)NROW * DIMK) + (size_t)row * (DIMK / 4) + lane;
    float4 a = *r0;
    float4 b = *r1;

    float s00 = a.x * a.x + a.y * a.y + a.z * a.z + a.w * a.w;
    float s11 = b.x * b.x + b.y * b.y + b.z * b.z + b.w * b.w;
    float s01 = a.x * b.x + a.y * b.y + a.z * b.z + a.w * b.w;
#pragma unroll
    for (int m = 16; m; m >>= 1) {
        s00 += __shfl_xor_sync(0xffffffffu, s00, m);
        s11 += __shfl_xor_sync(0xffffffffu, s11, m);
        s01 += __shfl_xor_sync(0xffffffffu, s01, m);
    }
    // matches F.normalize: x / max(||x||, eps)
    float inv0 = 1.0f / fmaxf(sqrtf(s00), 1e-12f);
    float inv1 = 1.0f / fmaxf(sqrtf(s11), 1e-12f);
    float inv0s = inv0 * K_EXP2;   // fold exp scale into v1

    __nv_bfloat162* o1 = (__nv_bfloat162*)g_v1 + (size_t)row * (DIMK / 2) + lane * 2;
    __nv_bfloat162* o2 = (__nv_bfloat162*)g_v2 + (size_t)row * (DIMK / 2) + lane * 2;
    o1[0] = __floats2bfloat162_rn(a.x * inv0s, a.y * inv0s);
    o1[1] = __floats2bfloat162_rn(a.z * inv0s, a.w * inv0s);
    o2[0] = __floats2bfloat162_rn(b.x * inv1, b.y * inv1);
    o2[1] = __floats2bfloat162_rn(b.z * inv1, b.w * inv1);

    if (lane == 0) {
        g_rowsum[row] = 0.0f;
        sh_diag[wid] = s01 * inv0 * inv1;   // exact fp32 diagonal (unscaled)
    }
    if (blockIdx.x == 0 && threadIdx.x == 0) out[0] = 0.0f;
    __syncthreads();
    if (threadIdx.x == 0)
        g_diag_part[blockIdx.x] = sh_diag[0] + sh_diag[1] + sh_diag[2] + sh_diag[3];
}

// Load one 128x128 bf16 tile (src row block) into swizzled smem: 8 chunks/thread.
__device__ __forceinline__ void issue_tile(uint32_t sDst, const __nv_bfloat16* gsrc,
                                           int tid) {
    const uint4* src = (const uint4*)gsrc;
#pragma unroll
    for (int it = 0; it < 8; it++) {
        int ci = tid + it * 256;
        int row = ci >> 4, c = ci & 15;
        uint32_t off = (uint32_t)row * 256u + (uint32_t)((c ^ (row & 7)) << 4);
        cp_async16(sDst + off, src + ci);
    }
}

// ---------------------------------------------------------------------------
// Kernel 2: persistent fused GEMM + exp + per-row sums.
// 296 CTAs; CTA c owns ~55 consecutive tiles t = m*128+n (<=2 row segments).
// Per segment: A(m) loaded ONCE (stays resident), B double-buffered — B(t+1)
// issued at the top of tile t's iteration so it streams during the mainloop.
// SMEM: A 32KB + B0 32KB + B1 32KB = 96KB -> 2 CTAs/SM.
// 8 warps in 4(m) x 2(n) grid; warp tile 32x64 = 2x8 m16n8k16 tiles.
// Epilogue: f16x2 exp per tile accumulated into 4 fp32 regs; shfl+atomic
// flush once per segment (no per-tile reduction/atomics).
// ---------------------------------------------------------------------------
__global__ void __launch_bounds__(256, 2) cl_gemm() {
    extern __shared__ __align__(1024) char smem[];
    const uint32_t sA  = smem_u32(smem);
    const uint32_t sB0 = sA + 32768u;
    const uint32_t sB1 = sA + 65536u;

    int tid = threadIdx.x, wid = tid >> 5, lane = tid & 31;

    int wm = wid & 3;        // warp row in 4x2 grid
    int wn = wid >> 2;       // warp col
    int row_base = wm * 32;
    int col_base = wn * 64;

    int lr = lane & 7;
    int q  = lane >> 3;

    // A fragment rows: lanes 0-7 rows 0-7, 8-15 rows 8-15 (k lo),
    // 16-23 rows 0-7, 24-31 rows 8-15 (k hi)
    int arow0 = row_base + (q & 1) * 8 + lr;         // mt = 0
    int arow1 = arow0 + 16;                          // mt = 1
    int aqk   = q >> 1;
    // B fragment rows: lanes 0-15 n 0-7 (k lo/hi), 16-31 n 8-15
    int brow_r = col_base + (q >> 1) * 8 + lr;
    int bqk   = q & 1;

    const uint32_t aBase0 = sA + (uint32_t)arow0 * 256u;
    const uint32_t aBase1 = sA + (uint32_t)arow1 * 256u;
    const uint32_t aSw0 = (uint32_t)(arow0 & 7);
    const uint32_t aSw1 = (uint32_t)(arow1 & 7);

    // Work range: CTA c gets 55 (+1 for c<104) consecutive tiles.
    int c = blockIdx.x;
    int start = c * 55 + min(c, 104);
    int end = start + 55 + (c < 104 ? 1 : 0);

    int t = start;
    while (t < end) {
        int m = t >> 7;
        int segEnd = min(end, (m + 1) * 128);

        // Segment prologue: A(m) + B(t) in one group, fully waited.
        issue_tile(sA, g_v1 + (size_t)m * 128 * DIMK, tid);
        issue_tile(sB0, g_v2 + (size_t)(t & 127) * 128 * DIMK, tid);
        asm volatile("cp.async.commit_group;" ::: "memory");
        asm volatile("cp.async.wait_group 0;" ::: "memory");
        __syncthreads();

        // Per-thread fp32 row accumulators for this segment:
        // rs[mt*2+half] -> row m*128 + row_base + mt*16 + (lane>>2) + half*8
        float rs0 = 0.0f, rs1 = 0.0f, rs2 = 0.0f, rs3 = 0.0f;

        int nIdx = 0;
        for (; t < segEnd; t++, nIdx++) {
            uint32_t curB = (nIdx & 1) ? sB1 : sB0;
            uint32_t nxtB = (nIdx & 1) ? sB0 : sB1;

            if (t + 1 < segEnd) {
                issue_tile(nxtB, g_v2 + (size_t)((t + 1) & 127) * 128 * DIMK, tid);
                asm volatile("cp.async.commit_group;" ::: "memory");
                asm volatile("cp.async.wait_group 1;" ::: "memory");
            } else {
                asm volatile("cp.async.wait_group 0;" ::: "memory");
            }
            __syncthreads();

            float acc[2][8][4];
#pragma unroll
            for (int mt = 0; mt < 2; mt++)
#pragma unroll
                for (int nt = 0; nt < 8; nt++)
#pragma unroll
                    for (int k = 0; k < 4; k++) acc[mt][nt][k] = 0.0f;

            // ---- mainloop: 8 k-steps ----
#pragma unroll
            for (int s = 0; s < 8; s++) {
                uint32_t a0[4], a1[4];
                {
                    uint32_t kch = (uint32_t)(s * 2 + aqk);
                    ldsm4(a0, aBase0 + ((kch ^ aSw0) << 4));
                    ldsm4(a1, aBase1 + ((kch ^ aSw1) << 4));
                }
                uint32_t b[4][4];
                uint32_t kchB = (uint32_t)(s * 2 + bqk);
#pragma unroll
                for (int nt2 = 0; nt2 < 4; nt2++) {
                    int nr = brow_r + nt2 * 16;
                    ldsm4(b[nt2], curB + (uint32_t)nr * 256u + ((kchB ^ (uint32_t)(nr & 7)) << 4));
                }
#pragma unroll
                for (int nt2 = 0; nt2 < 4; nt2++) {
#pragma unroll
                    for (int h = 0; h < 2; h++) {
                        int nt = nt2 * 2 + h;
                        mma16816(acc[0][nt], a0, b[nt2] + h * 2);
                        mma16816(acc[1][nt], a1, b[nt2] + h * 2);
                    }
                }
            }

            // smem reads for this tile done -> next iteration may overwrite nxtB
            __syncthreads();

            // ---- per-tile epilogue: f16x2 exp, accumulate into fp32 regs ----
#pragma unroll
            for (int mt = 0; mt < 2; mt++) {
                __half2 h0 = __floats2half2_rn(0.0f, 0.0f);
                __half2 h1 = __floats2half2_rn(0.0f, 0.0f);
#pragma unroll
                for (int nt = 0; nt < 8; nt++) {
                    uint32_t p0 = ex2_f16x2(cvt_f16x2(acc[mt][nt][0], acc[mt][nt][1]));
                    uint32_t p1 = ex2_f16x2(cvt_f16x2(acc[mt][nt][2], acc[mt][nt][3]));
                    h0 = __hadd2(h0, *(__half2*)&p0);
                    h1 = __hadd2(h1, *(__half2*)&p1);
                }
                float e0 = __low2float(h0) + __high2float(h0);
                float e1 = __low2float(h1) + __high2float(h1);
                if (mt == 0) { rs0 += e0; rs1 += e1; }
                else         { rs2 += e0; rs3 += e1; }
            }
        }

        // ---- segment flush: quad-reduce + one atomicAdd per row ----
        rs0 += __shfl_xor_sync(0xffffffffu, rs0, 1);
        rs0 += __shfl_xor_sync(0xffffffffu, rs0, 2);
        rs1 += __shfl_xor_sync(0xffffffffu, rs1, 1);
        rs1 += __shfl_xor_sync(0xffffffffu, rs1, 2);
        rs2 += __shfl_xor_sync(0xffffffffu, rs2, 1);
        rs2 += __shfl_xor_sync(0xffffffffu, rs2, 2);
        rs3 += __shfl_xor_sync(0xffffffffu, rs3, 1);
        rs3 += __shfl_xor_sync(0xffffffffu, rs3, 2);
        if ((lane & 3) == 0) {
            int gr = m * 128 + row_base + (lane >> 2);
            atomicAdd(&g_rowsum[gr], rs0);
            atomicAdd(&g_rowsum[gr + 8], rs1);
            atomicAdd(&g_rowsum[gr + 16], rs2);
            atomicAdd(&g_rowsum[gr + 24], rs3);
        }
    }
}

// ---------------------------------------------------------------------------
// Kernel 3: loss = sum_i log(rowsum_i) - (sum diag partials)/T
// 64 blocks x 256 threads: one row per thread; block partial -> atomicAdd.
// ---------------------------------------------------------------------------
__global__ void __launch_bounds__(256) cl_finalize(float* __restrict__ out) {
    __shared__ float sh[256];
    int tid = threadIdx.x;
    int i = blockIdx.x * 256 + tid;              // 0..16383
    float s = __logf(g_rowsum[i]);
    if (i < NROW / 4) s -= 5.0f * g_diag_part[i];
    sh[tid] = s;
    __syncthreads();
    for (int d = 128; d > 0; d >>= 1) {
        if (tid < d) sh[tid] += sh[tid + d];
        __syncthreads();
    }
    if (tid == 0) atomicAdd(out, sh[0]);
}

// ---------------------------------------------------------------------------
extern "C" void kernel_launch(void* const* d_in, const int* in_sizes, int n_in,
                              void* d_out, int out_size) {
    (void)in_sizes; (void)n_in; (void)out_size;
    const float* emb = (const float*)d_in[0];
    float* out = (float*)d_out;

    cudaFuncSetAttribute(cl_gemm, cudaFuncAttributeMaxDynamicSharedMemorySize,
                         98304);

    cl_prep<<<NROW / 4, 128>>>(emb, out);
    cl_gemm<<<NCTA, 256, 98304>>>();
    cl_finalize<<<NROW / 256, 256>>>(out);
}

// round 15
// speedup vs baseline: 1.1135x; 1.1135x over previous
#include <cuda_runtime.h>
#include <cuda_bf16.h>
#include <cuda_fp16.h>
#include <cstdint>

// Problem constants
#define NROW 16384
#define DIMK 128
#define NDIAG 2048          // diag partial blocks (prep grid size)

// log2(e) * 5  (exp(x/T) = 2^(x*5*log2e), T = 0.2) — folded into v1 at prep.
#define K_EXP2 7.2134752044448170f

// Scratch (static device globals — no runtime allocation)
static __device__ __align__(16) __nv_bfloat16 g_v1[NROW * DIMK];  // pre-scaled by K_EXP2
static __device__ __align__(16) __nv_bfloat16 g_v2[NROW * DIMK];
static __device__ float g_rowsum[NROW];
static __device__ float g_diag_part[NDIAG];

__device__ __forceinline__ uint32_t smem_u32(const void* p) {
    uint32_t a;
    asm("{ .reg .u64 t; cvta.to.shared.u64 t, %1; cvt.u32.u64 %0, t; }"
        : "=r"(a) : "l"(p));
    return a;
}

__device__ __forceinline__ void cp_async16(uint32_t smem_dst, const void* gsrc) {
    asm volatile("cp.async.cg.shared.global [%0], [%1], 16;"
                 :: "r"(smem_dst), "l"(gsrc) : "memory");
}

__device__ __forceinline__ void ldsm4(uint32_t* r, uint32_t addr) {
    asm volatile("ldmatrix.sync.aligned.m8n8.x4.shared.b16 {%0,%1,%2,%3}, [%4];"
                 : "=r"(r[0]), "=r"(r[1]), "=r"(r[2]), "=r"(r[3]) : "r"(addr));
}

__device__ __forceinline__ void mma16816(float* d, const uint32_t* a, const uint32_t* b) {
    asm volatile(
        "mma.sync.aligned.m16n8k16.row.col.f32.bf16.bf16.f32 "
        "{%0,%1,%2,%3}, {%4,%5,%6,%7}, {%8,%9}, {%0,%1,%2,%3};"
        : "+f"(d[0]), "+f"(d[1]), "+f"(d[2]), "+f"(d[3])
        : "r"(a[0]), "r"(a[1]), "r"(a[2]), "r"(a[3]), "r"(b[0]), "r"(b[1]));
}

// pack two f32 into f16x2 (single SASS cvt), exp2 on the pair (single MUFU op)
__device__ __forceinline__ uint32_t cvt_f16x2(float lo, float hi) {
    uint32_t r;
    asm("cvt.rn.f16x2.f32 %0, %1, %2;" : "=r"(r) : "f"(hi), "f"(lo));
    return r;
}
__device__ __forceinline__ uint32_t ex2_f16x2(uint32_t x) {
    uint32_t r;
    asm("ex2.approx.f16x2 %0, %1;" : "=r"(r) : "r"(x));
    return r;
}

// ---------------------------------------------------------------------------
// Kernel 1: normalize rows (fp32), emit bf16 copies (v1 pre-scaled by K_EXP2),
// per-block diag partials (fp32-exact), zero g_rowsum, zero out[0].
// Each warp handles TWO rows with all 4 global loads batched up front (MLP=4)
// to better overlap DRAM latency; 4 warps per block, 2048 blocks.
// ---------------------------------------------------------------------------
__global__ void __launch_bounds__(128) cl_prep(const float* __restrict__ emb,
                                               float* __restrict__ out) {
    __shared__ float sh_diag[8];
    int wid = threadIdx.x >> 5, lane = threadIdx.x & 31;
    int r0 = (blockIdx.x * 4 + wid) * 2;
    int r1 = r0 + 1;

    const float4* e0 = (const float4*)emb;                              // v1 rows
    const float4* e1 = (const float4*)(emb + (size_t)NROW * DIMK);      // v2 rows
    // 4 independent loads issued back-to-back (MLP = 4)
    float4 a0 = e0[(size_t)r0 * 32 + lane];
    float4 b0 = e1[(size_t)r0 * 32 + lane];
    float4 a1 = e0[(size_t)r1 * 32 + lane];
    float4 b1 = e1[(size_t)r1 * 32 + lane];

    float s00a = a0.x * a0.x + a0.y * a0.y + a0.z * a0.z + a0.w * a0.w;
    float s11a = b0.x * b0.x + b0.y * b0.y + b0.z * b0.z + b0.w * b0.w;
    float s01a = a0.x * b0.x + a0.y * b0.y + a0.z * b0.z + a0.w * b0.w;
    float s00b = a1.x * a1.x + a1.y * a1.y + a1.z * a1.z + a1.w * a1.w;
    float s11b = b1.x * b1.x + b1.y * b1.y + b1.z * b1.z + b1.w * b1.w;
    float s01b = a1.x * b1.x + a1.y * b1.y + a1.z * b1.z + a1.w * b1.w;
#pragma unroll
    for (int m = 16; m; m >>= 1) {
        s00a += __shfl_xor_sync(0xffffffffu, s00a, m);
        s11a += __shfl_xor_sync(0xffffffffu, s11a, m);
        s01a += __shfl_xor_sync(0xffffffffu, s01a, m);
        s00b += __shfl_xor_sync(0xffffffffu, s00b, m);
        s11b += __shfl_xor_sync(0xffffffffu, s11b, m);
        s01b += __shfl_xor_sync(0xffffffffu, s01b, m);
    }
    // matches F.normalize: x / max(||x||, eps)
    float i0a = 1.0f / fmaxf(sqrtf(s00a), 1e-12f);
    float i1a = 1.0f / fmaxf(sqrtf(s11a), 1e-12f);
    float i0b = 1.0f / fmaxf(sqrtf(s00b), 1e-12f);
    float i1b = 1.0f / fmaxf(sqrtf(s11b), 1e-12f);
    float i0as = i0a * K_EXP2;   // fold exp scale into v1
    float i0bs = i0b * K_EXP2;

    __nv_bfloat162* o1a = (__nv_bfloat162*)g_v1 + (size_t)r0 * (DIMK / 2) + lane * 2;
    __nv_bfloat162* o2a = (__nv_bfloat162*)g_v2 + (size_t)r0 * (DIMK / 2) + lane * 2;
    __nv_bfloat162* o1b = (__nv_bfloat162*)g_v1 + (size_t)r1 * (DIMK / 2) + lane * 2;
    __nv_bfloat162* o2b = (__nv_bfloat162*)g_v2 + (size_t)r1 * (DIMK / 2) + lane * 2;
    o1a[0] = __floats2bfloat162_rn(a0.x * i0as, a0.y * i0as);
    o1a[1] = __floats2bfloat162_rn(a0.z * i0as, a0.w * i0as);
    o2a[0] = __floats2bfloat162_rn(b0.x * i1a, b0.y * i1a);
    o2a[1] = __floats2bfloat162_rn(b0.z * i1a, b0.w * i1a);
    o1b[0] = __floats2bfloat162_rn(a1.x * i0bs, a1.y * i0bs);
    o1b[1] = __floats2bfloat162_rn(a1.z * i0bs, a1.w * i0bs);
    o2b[0] = __floats2bfloat162_rn(b1.x * i1b, b1.y * i1b);
    o2b[1] = __floats2bfloat162_rn(b1.z * i1b, b1.w * i1b);

    if (lane == 0) {
        g_rowsum[r0] = 0.0f;
        g_rowsum[r1] = 0.0f;
        sh_diag[wid * 2]     = s01a * i0a * i1a;   // exact fp32 diagonal terms
        sh_diag[wid * 2 + 1] = s01b * i0b * i1b;
    }
    if (blockIdx.x == 0 && threadIdx.x == 0) out[0] = 0.0f;
    __syncthreads();
    if (threadIdx.x == 0) {
        float d = 0.0f;
#pragma unroll
        for (int i = 0; i < 8; i++) d += sh_diag[i];
        g_diag_part[blockIdx.x] = d;
    }
}

// ---------------------------------------------------------------------------
// Kernel 2: fused GEMM tile (mma.sync bf16 HMMA) + exp + per-row sums.
// CTA = 128x128 tile of (K_EXP2*sim) = (K_EXP2*v1) @ v2^T, K=128 in smem.
// 8 warps in 4(m) x 2(n) grid; warp tile 32x64 = 2x8 m16n8k16 tiles.
// SMEM: row-major [128][128] bf16, 16B chunks XOR-swizzled: c' = c ^ (row&7).
// Mainloop software-pipelined (R10). Epilogue uses packed f16x2 ex2 to halve
// MUFU issue. 2 CTAs/SM so load phases overlap the other CTA's compute.
// (Unchanged from the 184.7us champion.)
// ---------------------------------------------------------------------------
__global__ void __launch_bounds__(256, 2) cl_gemm() {
    extern __shared__ __align__(1024) char smem[];
    const uint32_t sA = smem_u32(smem);
    const uint32_t sB = sA + 32768u;

    int tid = threadIdx.x, wid = tid >> 5, lane = tid & 31;
    int tile_n = blockIdx.x, tile_m = blockIdx.y;

    // ---- global -> smem via cp.async (swizzled), 8 x 16B per thread/tile ----
    const uint4* asrc = (const uint4*)(g_v1 + (size_t)tile_m * 128 * DIMK);
    const uint4* bsrc = (const uint4*)(g_v2 + (size_t)tile_n * 128 * DIMK);
#pragma unroll
    for (int it = 0; it < 8; it++) {
        int ci = tid + it * 256;
        int row = ci >> 4, c = ci & 15;
        uint32_t off = (uint32_t)row * 256u + (uint32_t)((c ^ (row & 7)) << 4);
        cp_async16(sA + off, asrc + ci);
        cp_async16(sB + off, bsrc + ci);
    }
    asm volatile("cp.async.commit_group;" ::: "memory");
    asm volatile("cp.async.wait_group 0;" ::: "memory");
    __syncthreads();

    int wm = wid & 3;        // warp row in 4x2 grid
    int wn = wid >> 2;       // warp col
    int row_base = wm * 32;
    int col_base = wn * 64;

    float acc[2][8][4];
#pragma unroll
    for (int mt = 0; mt < 2; mt++)
#pragma unroll
        for (int nt = 0; nt < 8; nt++)
#pragma unroll
            for (int k = 0; k < 4; k++) acc[mt][nt][k] = 0.0f;

    int lr = lane & 7;
    int q  = lane >> 3;

    // A fragment rows: lanes 0-7 rows 0-7, 8-15 rows 8-15 (k lo),
    // 16-23 rows 0-7, 24-31 rows 8-15 (k hi)
    int arow0 = row_base + (q & 1) * 8 + lr;         // mt = 0
    int arow1 = arow0 + 16;                          // mt = 1
    int aqk   = q >> 1;
    // B fragment rows: lanes 0-15 n 0-7 (k lo/hi), 16-31 n 8-15
    int brow_r = col_base + (q >> 1) * 8 + lr;
    int bqk   = q & 1;

    const uint32_t aBase0 = sA + (uint32_t)arow0 * 256u;
    const uint32_t aBase1 = sA + (uint32_t)arow1 * 256u;
    const uint32_t aSw0 = (uint32_t)(arow0 & 7);
    const uint32_t aSw1 = (uint32_t)(arow1 & 7);

    uint32_t aF[2][2][4];   // [buffer][mt][frag]

    // prologue: A fragments for s = 0
    {
        uint32_t kch = (uint32_t)aqk;
        ldsm4(aF[0][0], aBase0 + ((kch ^ aSw0) << 4));
        ldsm4(aF[0][1], aBase1 + ((kch ^ aSw1) << 4));
    }

#pragma unroll
    for (int s = 0; s < 8; s++) {
        const int cur = s & 1, nxt = cur ^ 1;
        uint32_t kchB = (uint32_t)(s * 2 + bqk);
        uint32_t b[4][4];

        {
            int nr0 = brow_r;
            int nr1 = brow_r + 16;
            ldsm4(b[0], sB + (uint32_t)nr0 * 256u + ((kchB ^ (uint32_t)(nr0 & 7)) << 4));
            ldsm4(b[1], sB + (uint32_t)nr1 * 256u + ((kchB ^ (uint32_t)(nr1 & 7)) << 4));
        }
        mma16816(acc[0][0], aF[cur][0], b[0]);
        mma16816(acc[1][0], aF[cur][1], b[0]);
        mma16816(acc[0][1], aF[cur][0], b[0] + 2);
        mma16816(acc[1][1], aF[cur][1], b[0] + 2);
        {
            int nr = brow_r + 32;
            ldsm4(b[2], sB + (uint32_t)nr * 256u + ((kchB ^ (uint32_t)(nr & 7)) << 4));
        }
        mma16816(acc[0][2], aF[cur][0], b[1]);
        mma16816(acc[1][2], aF[cur][1], b[1]);
        mma16816(acc[0][3], aF[cur][0], b[1] + 2);
        mma16816(acc[1][3], aF[cur][1], b[1] + 2);
        {
            int nr = brow_r + 48;
            ldsm4(b[3], sB + (uint32_t)nr * 256u + ((kchB ^ (uint32_t)(nr & 7)) << 4));
        }
        mma16816(acc[0][4], aF[cur][0], b[2]);
        mma16816(acc[1][4], aF[cur][1], b[2]);
        mma16816(acc[0][5], aF[cur][0], b[2] + 2);
        mma16816(acc[1][5], aF[cur][1], b[2] + 2);
        if (s < 7) {
            uint32_t kchA = (uint32_t)((s + 1) * 2 + aqk);
            ldsm4(aF[nxt][0], aBase0 + ((kchA ^ aSw0) << 4));
            ldsm4(aF[nxt][1], aBase1 + ((kchA ^ aSw1) << 4));
        }
        mma16816(acc[0][6], aF[cur][0], b[3]);
        mma16816(acc[1][6], aF[cur][1], b[3]);
        mma16816(acc[0][7], aF[cur][0], b[3] + 2);
        mma16816(acc[1][7], aF[cur][1], b[3] + 2);
    }

    // ---- epilogue: packed f16x2 exp (scale pre-folded) + row sums ----
    // m16n8 accum layout: d0,d1 -> row (lane>>2), d2,d3 -> row (lane>>2)+8.
#pragma unroll
    for (int mt = 0; mt < 2; mt++) {
        __half2 h0 = __floats2half2_rn(0.0f, 0.0f);
        __half2 h1 = __floats2half2_rn(0.0f, 0.0f);
#pragma unroll
        for (int nt = 0; nt < 8; nt++) {
            uint32_t p0 = ex2_f16x2(cvt_f16x2(acc[mt][nt][0], acc[mt][nt][1]));
            uint32_t p1 = ex2_f16x2(cvt_f16x2(acc[mt][nt][2], acc[mt][nt][3]));
            h0 = __hadd2(h0, *(__half2*)&p0);
            h1 = __hadd2(h1, *(__half2*)&p1);
        }
        float s0 = __low2float(h0) + __high2float(h0);
        float s1 = __low2float(h1) + __high2float(h1);
        s0 += __shfl_xor_sync(0xffffffffu, s0, 1);
        s0 += __shfl_xor_sync(0xffffffffu, s0, 2);
        s1 += __shfl_xor_sync(0xffffffffu, s1, 1);
        s1 += __shfl_xor_sync(0xffffffffu, s1, 2);
        if ((lane & 3) == 0) {
            int gr = tile_m * 128 + row_base + mt * 16 + (lane >> 2);
            atomicAdd(&g_rowsum[gr], s0);
            atomicAdd(&g_rowsum[gr + 8], s1);
        }
    }
}

// ---------------------------------------------------------------------------
// Kernel 3: loss = sum_i log(rowsum_i) - (sum diag partials)/T
// 64 blocks x 256 threads: one row per thread; block partial -> atomicAdd.
// ---------------------------------------------------------------------------
__global__ void __launch_bounds__(256) cl_finalize(float* __restrict__ out) {
    __shared__ float sh[256];
    int tid = threadIdx.x;
    int i = blockIdx.x * 256 + tid;              // 0..16383
    float s = __logf(g_rowsum[i]);
    if (i < NDIAG) s -= 5.0f * g_diag_part[i];
    sh[tid] = s;
    __syncthreads();
    for (int d = 128; d > 0; d >>= 1) {
        if (tid < d) sh[tid] += sh[tid + d];
        __syncthreads();
    }
    if (tid == 0) atomicAdd(out, sh[0]);
}

// ---------------------------------------------------------------------------
extern "C" void kernel_launch(void* const* d_in, const int* in_sizes, int n_in,
                              void* d_out, int out_size) {
    (void)in_sizes; (void)n_in; (void)out_size;
    const float* emb = (const float*)d_in[0];
    float* out = (float*)d_out;

    cudaFuncSetAttribute(cl_gemm, cudaFuncAttributeMaxDynamicSharedMemorySize,
                         65536);

    cl_prep<<<NDIAG, 128>>>(emb, out);
    cl_gemm<<<dim3(128, 128), 256, 65536>>>();
    cl_finalize<<<NROW / 256, 256>>>(out);
}

// round 16
// speedup vs baseline: 1.1235x; 1.0090x over previous
#include <cuda_runtime.h>
#include <cuda_bf16.h>
#include <cuda_fp16.h>
#include <cstdint>

// Problem constants
#define NROW 16384
#define DIMK 128
#define NDIAG 2048          // prep grid size (8 rows per block)

// log2(e) * 5  (exp(x/T) = 2^(x*5*log2e), T = 0.2) — folded into v1 at prep.
#define K_EXP2 7.2134752044448170f

// Scratch (static device globals — no runtime allocation)
static __device__ __align__(16) __nv_bfloat16 g_v1[NROW * DIMK];  // pre-scaled by K_EXP2
static __device__ __align__(16) __nv_bfloat16 g_v2[NROW * DIMK];
static __device__ float g_rowsum[NROW];
static __device__ float g_diag_part[NDIAG];

__device__ __forceinline__ uint32_t smem_u32(const void* p) {
    uint32_t a;
    asm("{ .reg .u64 t; cvta.to.shared.u64 t, %1; cvt.u32.u64 %0, t; }"
        : "=r"(a) : "l"(p));
    return a;
}

__device__ __forceinline__ void cp_async16(uint32_t smem_dst, const void* gsrc) {
    asm volatile("cp.async.cg.shared.global [%0], [%1], 16;"
                 :: "r"(smem_dst), "l"(gsrc) : "memory");
}

__device__ __forceinline__ void ldsm4(uint32_t* r, uint32_t addr) {
    asm volatile("ldmatrix.sync.aligned.m8n8.x4.shared.b16 {%0,%1,%2,%3}, [%4];"
                 : "=r"(r[0]), "=r"(r[1]), "=r"(r[2]), "=r"(r[3]) : "r"(addr));
}

__device__ __forceinline__ void mma16816(float* d, const uint32_t* a, const uint32_t* b) {
    asm volatile(
        "mma.sync.aligned.m16n8k16.row.col.f32.bf16.bf16.f32 "
        "{%0,%1,%2,%3}, {%4,%5,%6,%7}, {%8,%9}, {%0,%1,%2,%3};"
        : "+f"(d[0]), "+f"(d[1]), "+f"(d[2]), "+f"(d[3])
        : "r"(a[0]), "r"(a[1]), "r"(a[2]), "r"(a[3]), "r"(b[0]), "r"(b[1]));
}

// pack two f32 into f16x2 (single SASS cvt), exp2 on the pair (single MUFU op)
__device__ __forceinline__ uint32_t cvt_f16x2(float lo, float hi) {
    uint32_t r;
    asm("cvt.rn.f16x2.f32 %0, %1, %2;" : "=r"(r) : "f"(hi), "f"(lo));
    return r;
}
__device__ __forceinline__ uint32_t ex2_f16x2(uint32_t x) {
    uint32_t r;
    asm("ex2.approx.f16x2 %0, %1;" : "=r"(r) : "r"(x));
    return r;
}

// ---------------------------------------------------------------------------
// Kernel 1: normalize rows (fp32), emit bf16 copies (v1 pre-scaled by K_EXP2),
// per-block diag partials (fp32-exact), zero g_rowsum, zero out[0].
// One warp per row (the proven low-register shape); 8 warps per block.
// ---------------------------------------------------------------------------
__global__ void __launch_bounds__(256) cl_prep(const float* __restrict__ emb,
                                               float* __restrict__ out) {
    __shared__ float sh_diag[8];
    int wid = threadIdx.x >> 5, lane = threadIdx.x & 31;
    int row = blockIdx.x * 8 + wid;

    const float4* r0 = (const float4*)(emb) + (size_t)row * (DIMK / 4) + lane;
    const float4* r1 = (const float4*)(emb + (size_t)NROW * DIMK) + (size_t)row * (DIMK / 4) + lane;
    float4 a = *r0;
    float4 b = *r1;

    float s00 = a.x * a.x + a.y * a.y + a.z * a.z + a.w * a.w;
    float s11 = b.x * b.x + b.y * b.y + b.z * b.z + b.w * b.w;
    float s01 = a.x * b.x + a.y * b.y + a.z * b.z + a.w * b.w;
#pragma unroll
    for (int m = 16; m; m >>= 1) {
        s00 += __shfl_xor_sync(0xffffffffu, s00, m);
        s11 += __shfl_xor_sync(0xffffffffu, s11, m);
        s01 += __shfl_xor_sync(0xffffffffu, s01, m);
    }
    // matches F.normalize: x / max(||x||, eps)
    float inv0 = 1.0f / fmaxf(sqrtf(s00), 1e-12f);
    float inv1 = 1.0f / fmaxf(sqrtf(s11), 1e-12f);
    float inv0s = inv0 * K_EXP2;   // fold exp scale into v1

    __nv_bfloat162* o1 = (__nv_bfloat162*)g_v1 + (size_t)row * (DIMK / 2) + lane * 2;
    __nv_bfloat162* o2 = (__nv_bfloat162*)g_v2 + (size_t)row * (DIMK / 2) + lane * 2;
    o1[0] = __floats2bfloat162_rn(a.x * inv0s, a.y * inv0s);
    o1[1] = __floats2bfloat162_rn(a.z * inv0s, a.w * inv0s);
    o2[0] = __floats2bfloat162_rn(b.x * inv1, b.y * inv1);
    o2[1] = __floats2bfloat162_rn(b.z * inv1, b.w * inv1);

    if (lane == 0) {
        g_rowsum[row] = 0.0f;
        sh_diag[wid] = s01 * inv0 * inv1;   // exact fp32 diagonal (unscaled)
    }
    if (blockIdx.x == 0 && threadIdx.x == 0) out[0] = 0.0f;
    __syncthreads();
    if (threadIdx.x == 0) {
        float d = 0.0f;
#pragma unroll
        for (int i = 0; i < 8; i++) d += sh_diag[i];
        g_diag_part[blockIdx.x] = d;
    }
}

// ---------------------------------------------------------------------------
// Kernel 2: fused GEMM tile (mma.sync bf16 HMMA) + exp + per-row sums.
// CTA = 128x128 tile of (K_EXP2*sim) = (K_EXP2*v1) @ v2^T, K=128 in smem.
// 8 warps in 4(m) x 2(n) grid; warp tile 32x64 = 2x8 m16n8k16 tiles.
// SMEM: row-major [128][128] bf16, 16B chunks XOR-swizzled: c' = c ^ (row&7).
// Mainloop software-pipelined. Epilogue uses packed f16x2 ex2 to halve MUFU
// issue. 2 CTAs/SM so load phases overlap the other CTA's compute.
// (Byte-identical to the 184.7us champion gemm.)
// ---------------------------------------------------------------------------
__global__ void __launch_bounds__(256, 2) cl_gemm() {
    extern __shared__ __align__(1024) char smem[];
    const uint32_t sA = smem_u32(smem);
    const uint32_t sB = sA + 32768u;

    int tid = threadIdx.x, wid = tid >> 5, lane = tid & 31;
    int tile_n = blockIdx.x, tile_m = blockIdx.y;

    // ---- global -> smem via cp.async (swizzled), 8 x 16B per thread/tile ----
    const uint4* asrc = (const uint4*)(g_v1 + (size_t)tile_m * 128 * DIMK);
    const uint4* bsrc = (const uint4*)(g_v2 + (size_t)tile_n * 128 * DIMK);
#pragma unroll
    for (int it = 0; it < 8; it++) {
        int ci = tid + it * 256;
        int row = ci >> 4, c = ci & 15;
        uint32_t off = (uint32_t)row * 256u + (uint32_t)((c ^ (row & 7)) << 4);
        cp_async16(sA + off, asrc + ci);
        cp_async16(sB + off, bsrc + ci);
    }
    asm volatile("cp.async.commit_group;" ::: "memory");
    asm volatile("cp.async.wait_group 0;" ::: "memory");
    __syncthreads();

    int wm = wid & 3;        // warp row in 4x2 grid
    int wn = wid >> 2;       // warp col
    int row_base = wm * 32;
    int col_base = wn * 64;

    float acc[2][8][4];
#pragma unroll
    for (int mt = 0; mt < 2; mt++)
#pragma unroll
        for (int nt = 0; nt < 8; nt++)
#pragma unroll
            for (int k = 0; k < 4; k++) acc[mt][nt][k] = 0.0f;

    int lr = lane & 7;
    int q  = lane >> 3;

    // A fragment rows: lanes 0-7 rows 0-7, 8-15 rows 8-15 (k lo),
    // 16-23 rows 0-7, 24-31 rows 8-15 (k hi)
    int arow0 = row_base + (q & 1) * 8 + lr;         // mt = 0
    int arow1 = arow0 + 16;                          // mt = 1
    int aqk   = q >> 1;
    // B fragment rows: lanes 0-15 n 0-7 (k lo/hi), 16-31 n 8-15
    int brow_r = col_base + (q >> 1) * 8 + lr;
    int bqk   = q & 1;

    const uint32_t aBase0 = sA + (uint32_t)arow0 * 256u;
    const uint32_t aBase1 = sA + (uint32_t)arow1 * 256u;
    const uint32_t aSw0 = (uint32_t)(arow0 & 7);
    const uint32_t aSw1 = (uint32_t)(arow1 & 7);

    uint32_t aF[2][2][4];   // [buffer][mt][frag]

    // prologue: A fragments for s = 0
    {
        uint32_t kch = (uint32_t)aqk;
        ldsm4(aF[0][0], aBase0 + ((kch ^ aSw0) << 4));
        ldsm4(aF[0][1], aBase1 + ((kch ^ aSw1) << 4));
    }

#pragma unroll
    for (int s = 0; s < 8; s++) {
        const int cur = s & 1, nxt = cur ^ 1;
        uint32_t kchB = (uint32_t)(s * 2 + bqk);
        uint32_t b[4][4];

        {
            int nr0 = brow_r;
            int nr1 = brow_r + 16;
            ldsm4(b[0], sB + (uint32_t)nr0 * 256u + ((kchB ^ (uint32_t)(nr0 & 7)) << 4));
            ldsm4(b[1], sB + (uint32_t)nr1 * 256u + ((kchB ^ (uint32_t)(nr1 & 7)) << 4));
        }
        mma16816(acc[0][0], aF[cur][0], b[0]);
        mma16816(acc[1][0], aF[cur][1], b[0]);
        mma16816(acc[0][1], aF[cur][0], b[0] + 2);
        mma16816(acc[1][1], aF[cur][1], b[0] + 2);
        {
            int nr = brow_r + 32;
            ldsm4(b[2], sB + (uint32_t)nr * 256u + ((kchB ^ (uint32_t)(nr & 7)) << 4));
        }
        mma16816(acc[0][2], aF[cur][0], b[1]);
        mma16816(acc[1][2], aF[cur][1], b[1]);
        mma16816(acc[0][3], aF[cur][0], b[1] + 2);
        mma16816(acc[1][3], aF[cur][1], b[1] + 2);
        {
            int nr = brow_r + 48;
            ldsm4(b[3], sB + (uint32_t)nr * 256u + ((kchB ^ (uint32_t)(nr & 7)) << 4));
        }
        mma16816(acc[0][4], aF[cur][0], b[2]);
        mma16816(acc[1][4], aF[cur][1], b[2]);
        mma16816(acc[0][5], aF[cur][0], b[2] + 2);
        mma16816(acc[1][5], aF[cur][1], b[2] + 2);
        if (s < 7) {
            uint32_t kchA = (uint32_t)((s + 1) * 2 + aqk);
            ldsm4(aF[nxt][0], aBase0 + ((kchA ^ aSw0) << 4));
            ldsm4(aF[nxt][1], aBase1 + ((kchA ^ aSw1) << 4));
        }
        mma16816(acc[0][6], aF[cur][0], b[3]);
        mma16816(acc[1][6], aF[cur][1], b[3]);
        mma16816(acc[0][7], aF[cur][0], b[3] + 2);
        mma16816(acc[1][7], aF[cur][1], b[3] + 2);
    }

    // ---- epilogue: packed f16x2 exp (scale pre-folded) + row sums ----
    // m16n8 accum layout: d0,d1 -> row (lane>>2), d2,d3 -> row (lane>>2)+8.
#pragma unroll
    for (int mt = 0; mt < 2; mt++) {
        __half2 h0 = __floats2half2_rn(0.0f, 0.0f);
        __half2 h1 = __floats2half2_rn(0.0f, 0.0f);
#pragma unroll
        for (int nt = 0; nt < 8; nt++) {
            uint32_t p0 = ex2_f16x2(cvt_f16x2(acc[mt][nt][0], acc[mt][nt][1]));
            uint32_t p1 = ex2_f16x2(cvt_f16x2(acc[mt][nt][2], acc[mt][nt][3]));
            h0 = __hadd2(h0, *(__half2*)&p0);
            h1 = __hadd2(h1, *(__half2*)&p1);
        }
        float s0 = __low2float(h0) + __high2float(h0);
        float s1 = __low2float(h1) + __high2float(h1);
        s0 += __shfl_xor_sync(0xffffffffu, s0, 1);
        s0 += __shfl_xor_sync(0xffffffffu, s0, 2);
        s1 += __shfl_xor_sync(0xffffffffu, s1, 1);
        s1 += __shfl_xor_sync(0xffffffffu, s1, 2);
        if ((lane & 3) == 0) {
            int gr = tile_m * 128 + row_base + mt * 16 + (lane >> 2);
            atomicAdd(&g_rowsum[gr], s0);
            atomicAdd(&g_rowsum[gr + 8], s1);
        }
    }
}

// ---------------------------------------------------------------------------
// Kernel 3: loss = sum_i log(rowsum_i) - (sum diag partials)/T
// 64 blocks x 256 threads: one row per thread; block partial -> atomicAdd.
// ---------------------------------------------------------------------------
__global__ void __launch_bounds__(256) cl_finalize(float* __restrict__ out) {
    __shared__ float sh[256];
    int tid = threadIdx.x;
    int i = blockIdx.x * 256 + tid;              // 0..16383
    float s = __logf(g_rowsum[i]);
    if (i < NDIAG) s -= 5.0f * g_diag_part[i];
    sh[tid] = s;
    __syncthreads();
    for (int d = 128; d > 0; d >>= 1) {
        if (tid < d) sh[tid] += sh[tid + d];
        __syncthreads();
    }
    if (tid == 0) atomicAdd(out, sh[0]);
}

// ---------------------------------------------------------------------------
extern "C" void kernel_launch(void* const* d_in, const int* in_sizes, int n_in,
                              void* d_out, int out_size) {
    (void)in_sizes; (void)n_in; (void)out_size;
    const float* emb = (const float*)d_in[0];
    float* out = (float*)d_out;

    cudaFuncSetAttribute(cl_gemm, cudaFuncAttributeMaxDynamicSharedMemorySize,
                         65536);

    cl_prep<<<NDIAG, 256>>>(emb, out);
    cl_gemm<<<dim3(128, 128), 256, 65536>>>();
    cl_finalize<<<NROW / 256, 256>>>(out);
}